// round 3
// baseline (speedup 1.0000x reference)
#include <cuda_runtime.h>
#include <cuda_fp16.h>
#include <cuda_pipeline.h>
#include <mma.h>

using namespace nvcuda;

#define B_  4
#define S_  2048
#define D_  1024
#define H_  16
#define HD_ 64
#define M_  (B_*S_)   // 8192

// ---------------- device scratch (no allocations allowed) ----------------
__device__ __half g_Xh [M_*D_];
__device__ __half g_Wqh[D_*D_];
__device__ __half g_Wkh[D_*D_];
__device__ __half g_Wvh[D_*D_];
__device__ __half g_Woh[D_*D_];
__device__ __half g_Qh [M_*D_];
__device__ __half g_Kh [M_*D_];
__device__ __half g_Vh [M_*D_];
__device__ __half g_Ah [M_*D_];

// ---------------- elementwise converter (4 float4 per thread for MLP) ----------------
__global__ void k_f32_to_f16(const float* __restrict__ src, __half* __restrict__ dst) {
    int base = blockIdx.x * 1024 + threadIdx.x;
    __half2* d2 = (__half2*)dst;
    #pragma unroll
    for (int it = 0; it < 4; it++) {
        int i = base + it * 256;
        float4 v = ((const float4*)src)[i];
        d2[2*i]   = __floats2half2_rn(v.x, v.y);
        d2[2*i+1] = __floats2half2_rn(v.z, v.w);
    }
}

// ---------------- fp16 WMMA GEMM with cp.async double buffering ----------------
// C[8192,1024] = A @ W + bias, fp32 accumulate, OutT output (half or float).
#define BM 128
#define BN 128
#define BK 64
#define LDA 72     // halves per A-tile row
#define LDB 136    // halves per B-tile row
#define LDBIAS 136 // floats per bias-tile row
#define A_TILE (BM * LDA)            // 9216 halves
#define B_TILE (BK * LDB)            // 8704 halves
#define STAGE_BYTES ((A_TILE + B_TILE) * 2)   // 35840 B per stage
#define GEMM_SMEM (2 * STAGE_BYTES + 16 * LDBIAS * 4)  // 80384 B

template <typename OutT>
__device__ __forceinline__ void gemm_body(
    char* smem_raw,
    const __half* __restrict__ A, const __half* __restrict__ Bw,
    const float* __restrict__ bias, OutT* __restrict__ C)
{
    const int Nn = D_, Kn = D_;
    __half* As[2]; __half* Bs[2];
    As[0] = (__half*)smem_raw;
    Bs[0] = As[0] + A_TILE;
    As[1] = Bs[0] + B_TILE;
    Bs[1] = As[1] + A_TILE;
    float* biasTile = (float*)(smem_raw + 2 * STAGE_BYTES);

    const int tid = threadIdx.x;
    const int m0  = blockIdx.y * BM;
    const int n0  = blockIdx.x * BN;
    const int w   = tid >> 5;
    const int wm  = w >> 1;      // 0..3 -> 32-row slab
    const int wn  = w & 1;       // 0..1 -> 64-col slab

    // bias tile: 16 identical rows of bias[n0..n0+BN)
    #pragma unroll
    for (int it = 0; it < 8; it++) {
        int idx = tid + it * 256;
        int r = idx >> 7, c = idx & 127;
        biasTile[r * LDBIAS + c] = bias[n0 + c];
    }

    auto load_stage = [&](int s, int k0) {
        #pragma unroll
        for (int it = 0; it < 4; it++) {
            int idx = tid + it * 256;
            int r = idx >> 3, c = (idx & 7) * 8;
            __pipeline_memcpy_async(&As[s][r * LDA + c],
                                    &A[(size_t)(m0 + r) * Kn + k0 + c], 16);
        }
        #pragma unroll
        for (int it = 0; it < 4; it++) {
            int idx = tid + it * 256;
            int r = idx >> 4, c = (idx & 15) * 8;
            __pipeline_memcpy_async(&Bs[s][r * LDB + c],
                                    &Bw[(size_t)(k0 + r) * Nn + n0 + c], 16);
        }
        __pipeline_commit();
    };

    load_stage(0, 0);
    __syncthreads();   // bias tile visible

    wmma::fragment<wmma::accumulator, 16, 16, 16, float> acc[2][4];
    #pragma unroll
    for (int i = 0; i < 2; i++)
        #pragma unroll
        for (int j = 0; j < 4; j++)
            wmma::load_matrix_sync(acc[i][j], &biasTile[wn * 64 + j * 16],
                                   LDBIAS, wmma::mem_row_major);

    const int nk = Kn / BK;
    for (int k0 = 0; k0 < nk; k0++) {
        const int cur = k0 & 1;
        if (k0 + 1 < nk) load_stage(cur ^ 1, (k0 + 1) * BK);
        __pipeline_wait_prior((k0 + 1 < nk) ? 1 : 0);
        __syncthreads();

        #pragma unroll
        for (int kk = 0; kk < BK / 16; kk++) {
            wmma::fragment<wmma::matrix_a, 16, 16, 16, __half, wmma::row_major> af[2];
            wmma::fragment<wmma::matrix_b, 16, 16, 16, __half, wmma::row_major> bf[4];
            #pragma unroll
            for (int i = 0; i < 2; i++)
                wmma::load_matrix_sync(af[i], &As[cur][(wm * 32 + i * 16) * LDA + kk * 16], LDA);
            #pragma unroll
            for (int j = 0; j < 4; j++)
                wmma::load_matrix_sync(bf[j], &Bs[cur][(kk * 16) * LDB + wn * 64 + j * 16], LDB);
            #pragma unroll
            for (int i = 0; i < 2; i++)
                #pragma unroll
                for (int j = 0; j < 4; j++)
                    wmma::mma_sync(acc[i][j], af[i], bf[j], acc[i][j]);
        }
        __syncthreads();
    }

    if constexpr (sizeof(OutT) == 4) {
        #pragma unroll
        for (int i = 0; i < 2; i++)
            #pragma unroll
            for (int j = 0; j < 4; j++) {
                int row = m0 + wm * 32 + i * 16;
                int col = n0 + wn * 64 + j * 16;
                wmma::store_matrix_sync((float*)&C[(size_t)row * Nn + col],
                                        acc[i][j], Nn, wmma::mem_row_major);
            }
    } else {
        float* stage = (float*)smem_raw;
        const int LDS_ = 68;
        float* my = stage + w * (32 * LDS_);
        #pragma unroll
        for (int i = 0; i < 2; i++)
            #pragma unroll
            for (int j = 0; j < 4; j++)
                wmma::store_matrix_sync(&my[(i * 16) * LDS_ + j * 16],
                                        acc[i][j], LDS_, wmma::mem_row_major);
        __syncthreads();
        #pragma unroll
        for (int it = 0; it < 32; it++) {
            int idx = tid + it * 256;
            int r = idx >> 6, c2 = idx & 63;
            int col = c2 * 2;
            int w2 = (r >> 5) * 2 + (col >> 6);
            const float* src = stage + w2 * (32 * LDS_) + (r & 31) * LDS_ + (col & 63);
            __half2 hv = __floats2half2_rn(src[0], src[1]);
            *(__half2*)&((__half*)C)[(size_t)(m0 + r) * Nn + n0 + col] = hv;
        }
    }
}

__global__ __launch_bounds__(256) void k_gemm_qkv(
    const __half* __restrict__ A,
    const __half* __restrict__ W0, const __half* __restrict__ W1, const __half* __restrict__ W2,
    const float* __restrict__ b0, const float* __restrict__ b1, const float* __restrict__ b2,
    __half* __restrict__ C0, __half* __restrict__ C1, __half* __restrict__ C2)
{
    extern __shared__ char smem_raw[];
    const int z = blockIdx.z;
    const __half* Bw = (z == 0) ? W0 : (z == 1) ? W1 : W2;
    const float* bias = (z == 0) ? b0 : (z == 1) ? b1 : b2;
    __half* C = (z == 0) ? C0 : (z == 1) ? C1 : C2;
    gemm_body<__half>(smem_raw, A, Bw, bias, C);
}

__global__ __launch_bounds__(256) void k_gemm_o(
    const __half* __restrict__ A, const __half* __restrict__ Bw,
    const float* __restrict__ bias, float* __restrict__ C)
{
    extern __shared__ char smem_raw[];
    gemm_body<float>(smem_raw, A, Bw, bias, C);
}

// ---------------- causal flash attention ----------------
// BQ=128 query rows per block, 8 warps, each warp owns a private 16-row slab.
// BKV=64 key tile, cp.async double-buffered, ONE __syncthreads per key iter.
#define AQ 128
#define AK 64
#define LDQ 72    // halves
#define LDK 72    // halves
#define LDSF 68   // floats (warp slab)
#define LDP 72    // halves (warp slab)
// smem: Q 18432 + K 2*9216 + V 2*9216 + S 8*16*68*4=34816 + P 8*16*72*2=18432
#define ATT_SMEM (AQ*LDQ*2 + 4*AK*LDK*2 + 8*16*LDSF*4 + 8*16*LDP*2)  // 108544

__global__ __launch_bounds__(256) void k_attention(
    const __half* __restrict__ Q, const __half* __restrict__ K,
    const __half* __restrict__ V, __half* __restrict__ Aout)
{
    extern __shared__ char smem_raw[];
    __half* Qs = (__half*)smem_raw;
    __half* Ks[2]; __half* Vs[2];
    Ks[0] = Qs + AQ * LDQ;
    Ks[1] = Ks[0] + AK * LDK;
    Vs[0] = Ks[1] + AK * LDK;
    Vs[1] = Vs[0] + AK * LDK;
    float*  Sw = (float*)(Vs[1] + AK * LDK);
    __half* Pw = (__half*)(Sw + 8 * 16 * LDSF);

    const int qb = blockIdx.x;
    const int h  = blockIdx.y;
    const int b  = blockIdx.z;
    const int tid  = threadIdx.x;
    const int w    = tid >> 5;
    const int lane = tid & 31;

    const size_t base = (size_t)b * S_ * D_ + (size_t)h * HD_;

    auto loadKV = [&](int s, int kb) {
        #pragma unroll
        for (int it = 0; it < 2; it++) {
            int idx = tid + it * 256;            // 0..511
            int r = idx >> 3, c = (idx & 7) * 8;
            __pipeline_memcpy_async(&Ks[s][r * LDK + c],
                                    &K[base + (size_t)(kb * AK + r) * D_ + c], 16);
            __pipeline_memcpy_async(&Vs[s][r * LDK + c],
                                    &V[base + (size_t)(kb * AK + r) * D_ + c], 16);
        }
        __pipeline_commit();
    };

    // prologue: Q tile (128x64 halves = 1024 x 16B) + KV stage 0, one group
    #pragma unroll
    for (int it = 0; it < 4; it++) {
        int idx = tid + it * 256;
        int r = idx >> 3, c = (idx & 7) * 8;
        __pipeline_memcpy_async(&Qs[r * LDQ + c],
                                &Q[base + (size_t)(qb * AQ + r) * D_ + c], 16);
    }
    {
        #pragma unroll
        for (int it = 0; it < 2; it++) {
            int idx = tid + it * 256;
            int r = idx >> 3, c = (idx & 7) * 8;
            __pipeline_memcpy_async(&Ks[0][r * LDK + c],
                                    &K[base + (size_t)(r) * D_ + c], 16);
            __pipeline_memcpy_async(&Vs[0][r * LDK + c],
                                    &V[base + (size_t)(r) * D_ + c], 16);
        }
        __pipeline_commit();
    }

    const int rloc  = lane >> 1;           // 0..15 (row within warp slab)
    const int c0    = (lane & 1) * 32;     // 32-col half
    const int qglob = qb * AQ + w * 16 + rloc;

    float* Ssl = Sw + w * (16 * LDSF);
    __half* Psl = Pw + w * (16 * LDP);

    float m = -INFINITY, l = 0.0f;
    float O[32];
    #pragma unroll
    for (int i = 0; i < 32; i++) O[i] = 0.0f;

    const int nkb = 2 * qb + 2;            // key blocks covering causal span
    for (int kb = 0; kb < nkb; kb++) {
        const int s = kb & 1;
        __pipeline_wait_prior(0);
        __syncthreads();                    // stage s ready; all warps done with s^1
        if (kb + 1 < nkb) loadKV(s ^ 1, kb + 1);

        // ---- S = Q(slab) @ K^T : 16x64, warp-private ----
        {
            wmma::fragment<wmma::accumulator, 16, 16, 16, float> sc[4];
            #pragma unroll
            for (int j = 0; j < 4; j++) wmma::fill_fragment(sc[j], 0.0f);
            #pragma unroll
            for (int kk = 0; kk < 4; kk++) {
                wmma::fragment<wmma::matrix_a, 16, 16, 16, __half, wmma::row_major> aq;
                wmma::load_matrix_sync(aq, &Qs[(w * 16) * LDQ + kk * 16], LDQ);
                #pragma unroll
                for (int j = 0; j < 4; j++) {
                    wmma::fragment<wmma::matrix_b, 16, 16, 16, __half, wmma::col_major> bk;
                    wmma::load_matrix_sync(bk, &Ks[s][(j * 16) * LDK + kk * 16], LDK);
                    wmma::mma_sync(sc[j], aq, bk, sc[j]);
                }
            }
            #pragma unroll
            for (int j = 0; j < 4; j++)
                wmma::store_matrix_sync(&Ssl[j * 16], sc[j], LDSF, wmma::mem_row_major);
        }
        __syncwarp();

        // ---- online softmax (warp-private; 2 lanes per row) ----
        {
            float sv[32];
            float tmax = -INFINITY;
            #pragma unroll
            for (int i = 0; i < 32; i++) {
                float x = Ssl[rloc * LDSF + c0 + i] * 0.125f;   // 1/sqrt(64)
                int kg = kb * AK + c0 + i;
                x = (kg <= qglob) ? x : -INFINITY;
                sv[i] = x;
                tmax = fmaxf(tmax, x);
            }
            tmax = fmaxf(tmax, __shfl_xor_sync(0xffffffffu, tmax, 1));
            float mnew  = fmaxf(m, tmax);
            float alpha = (m == -INFINITY) ? 0.0f : __expf(m - mnew);
            float psum = 0.0f;
            #pragma unroll
            for (int i = 0; i < 32; i++) {
                float p = (sv[i] == -INFINITY) ? 0.0f : __expf(sv[i] - mnew);
                psum += p;
                Psl[rloc * LDP + c0 + i] = __float2half(p);
            }
            psum += __shfl_xor_sync(0xffffffffu, psum, 1);
            l = l * alpha + psum;
            m = mnew;
            #pragma unroll
            for (int i = 0; i < 32; i++) O[i] *= alpha;
        }
        __syncwarp();

        // ---- PV = P(16x64) @ V(64x64), warp-private ----
        {
            wmma::fragment<wmma::accumulator, 16, 16, 16, float> pv[4];
            #pragma unroll
            for (int j = 0; j < 4; j++) wmma::fill_fragment(pv[j], 0.0f);
            #pragma unroll
            for (int kk = 0; kk < 4; kk++) {
                wmma::fragment<wmma::matrix_a, 16, 16, 16, __half, wmma::row_major> ap;
                wmma::load_matrix_sync(ap, &Psl[kk * 16], LDP);
                #pragma unroll
                for (int j = 0; j < 4; j++) {
                    wmma::fragment<wmma::matrix_b, 16, 16, 16, __half, wmma::row_major> bv;
                    wmma::load_matrix_sync(bv, &Vs[s][(kk * 16) * LDK + j * 16], LDK);
                    wmma::mma_sync(pv[j], ap, bv, pv[j]);
                }
            }
            #pragma unroll
            for (int j = 0; j < 4; j++)
                wmma::store_matrix_sync(&Ssl[j * 16], pv[j], LDSF, wmma::mem_row_major);
        }
        __syncwarp();
        #pragma unroll
        for (int i = 0; i < 32; i++) O[i] += Ssl[rloc * LDSF + c0 + i];
    }

    const float inv_l = 1.0f / l;
    const size_t orow = base + (size_t)(qb * AQ + w * 16 + rloc) * D_;
    #pragma unroll
    for (int i = 0; i < 32; i += 2) {
        __half2 hv = __floats2half2_rn(O[i] * inv_l, O[i + 1] * inv_l);
        *(__half2*)&Aout[orow + c0 + i] = hv;
    }
}

// ---------------- launch ----------------
extern "C" void kernel_launch(void* const* d_in, const int* in_sizes, int n_in,
                              void* d_out, int out_size)
{
    const float* hidden = (const float*)d_in[0];
    const float* Wq = (const float*)d_in[1];
    const float* bq = (const float*)d_in[2];
    const float* Wk = (const float*)d_in[3];
    const float* bk = (const float*)d_in[4];
    const float* Wv = (const float*)d_in[5];
    const float* bv = (const float*)d_in[6];
    const float* Wo = (const float*)d_in[7];
    const float* bo = (const float*)d_in[8];
    float* out = (float*)d_out;

    __half *Xh, *Wqh, *Wkh, *Wvh, *Woh, *Qh, *Kh, *Vh, *Ah;
    cudaGetSymbolAddress((void**)&Xh,  g_Xh);
    cudaGetSymbolAddress((void**)&Wqh, g_Wqh);
    cudaGetSymbolAddress((void**)&Wkh, g_Wkh);
    cudaGetSymbolAddress((void**)&Wvh, g_Wvh);
    cudaGetSymbolAddress((void**)&Woh, g_Woh);
    cudaGetSymbolAddress((void**)&Qh,  g_Qh);
    cudaGetSymbolAddress((void**)&Kh,  g_Kh);
    cudaGetSymbolAddress((void**)&Vh,  g_Vh);
    cudaGetSymbolAddress((void**)&Ah,  g_Ah);

    const int n4_full = M_ * D_ / 4;    // 2M float4
    const int n4_w    = D_ * D_ / 4;    // 256K float4

    // fp16 conversions (4 float4 / thread)
    k_f32_to_f16<<<n4_full / 1024, 256>>>(hidden, Xh);
    k_f32_to_f16<<<n4_w / 1024, 256>>>(Wq, Wqh);
    k_f32_to_f16<<<n4_w / 1024, 256>>>(Wk, Wkh);
    k_f32_to_f16<<<n4_w / 1024, 256>>>(Wv, Wvh);
    k_f32_to_f16<<<n4_w / 1024, 256>>>(Wo, Woh);

    cudaFuncSetAttribute(k_gemm_qkv, cudaFuncAttributeMaxDynamicSharedMemorySize, GEMM_SMEM);
    cudaFuncSetAttribute(k_gemm_o,   cudaFuncAttributeMaxDynamicSharedMemorySize, GEMM_SMEM);
    cudaFuncSetAttribute(k_attention, cudaFuncAttributeMaxDynamicSharedMemorySize, ATT_SMEM);

    // fused QKV projections (one launch, grid.z selects Q/K/V)
    dim3 qkvgrid(D_ / BN, M_ / BM, 3);   // (8, 64, 3)
    k_gemm_qkv<<<qkvgrid, 256, GEMM_SMEM>>>(Xh, Wqh, Wkh, Wvh, bq, bk, bv, Qh, Kh, Vh);

    // attention: 128-row query tiles
    k_attention<<<dim3(S_ / AQ, H_, B_), 256, ATT_SMEM>>>(Qh, Kh, Vh, Ah);

    // output projection: bias fused, fp32 straight to d_out
    dim3 ogrid(D_ / BN, M_ / BM);
    k_gemm_o<<<ogrid, 256, GEMM_SMEM>>>(Ah, Woh, bo, out);
}

// round 13
// speedup vs baseline: 1.2553x; 1.2553x over previous
#include <cuda_runtime.h>
#include <cuda_fp16.h>
#include <cuda_pipeline.h>
#include <mma.h>

using namespace nvcuda;

#define B_  4
#define S_  2048
#define D_  1024
#define H_  16
#define HD_ 64
#define M_  (B_*S_)   // 8192

// ---------------- device scratch ----------------
__device__ __half g_Xh [M_*D_];
__device__ __half g_Wqh[D_*D_];
__device__ __half g_Wkh[D_*D_];
__device__ __half g_Wvh[D_*D_];
__device__ __half g_Woh[D_*D_];
__device__ __half g_Qh [M_*D_];
__device__ __half g_Kh [M_*D_];
__device__ __half g_Vh [M_*D_];
__device__ __half g_Ah [M_*D_];

// ---------------- elementwise converter ----------------
__global__ void k_f32_to_f16(const float* __restrict__ src, __half* __restrict__ dst) {
    int base = blockIdx.x * 1024 + threadIdx.x;
    __half2* d2 = (__half2*)dst;
    #pragma unroll
    for (int it = 0; it < 4; it++) {
        int i = base + it * 256;
        float4 v = ((const float4*)src)[i];
        d2[2*i]   = __floats2half2_rn(v.x, v.y);
        d2[2*i+1] = __floats2half2_rn(v.z, v.w);
    }
}

// ---------------- fp16 WMMA GEMM, 4 warps, 64x64 per warp ----------------
#define BM 128
#define BN 128
#define BK 64
#define LDA 72     // halves per A-tile row
#define LDB 136    // halves per B-tile row
#define LDBIAS 136
#define A_TILE (BM * LDA)            // 9216 halves
#define B_TILE (BK * LDB)            // 8704 halves
#define STAGE_H (A_TILE + B_TILE)    // 17920 halves
#define GEMM_SMEM (2 * STAGE_H * 2 + 16 * LDBIAS * 4)  // 80384 B

template <typename OutT>
__device__ __forceinline__ void gemm_body(
    char* smem_raw,
    const __half* __restrict__ A, const __half* __restrict__ Bw,
    const float* __restrict__ bias, OutT* __restrict__ C)
{
    __half* As[2]; __half* Bs[2];
    As[0] = (__half*)smem_raw;
    Bs[0] = As[0] + A_TILE;
    As[1] = Bs[0] + B_TILE;
    Bs[1] = As[1] + A_TILE;
    float* biasTile = (float*)(smem_raw + 2 * STAGE_H * 2);

    const int Nn = D_, Kn = D_;
    const int tid = threadIdx.x;
    const int m0  = blockIdx.y * BM;
    const int n0  = blockIdx.x * BN;
    const int w   = tid >> 5;
    const int wm  = w >> 1;      // 0..1 -> 64-row slab
    const int wn  = w & 1;       // 0..1 -> 64-col slab

    // bias tile: 16 identical rows of bias[n0..n0+BN)
    #pragma unroll
    for (int it = 0; it < 16; it++) {
        int idx = tid + it * 128;          // 0..2047
        int r = idx >> 7, c = idx & 127;
        biasTile[r * LDBIAS + c] = bias[n0 + c];
    }

    auto load_stage = [&](int s, int k0) {
        #pragma unroll
        for (int it = 0; it < 8; it++) {
            int idx = tid + it * 128;      // 1024 float4 for A
            int r = idx >> 3, c = (idx & 7) * 8;
            __pipeline_memcpy_async(&As[s][r * LDA + c],
                                    &A[(size_t)(m0 + r) * Kn + k0 + c], 16);
        }
        #pragma unroll
        for (int it = 0; it < 8; it++) {
            int idx = tid + it * 128;      // 1024 float4 for B
            int r = idx >> 4, c = (idx & 15) * 8;
            __pipeline_memcpy_async(&Bs[s][r * LDB + c],
                                    &Bw[(size_t)(k0 + r) * Nn + n0 + c], 16);
        }
        __pipeline_commit();
    };

    load_stage(0, 0);
    __syncthreads();   // bias tile visible

    wmma::fragment<wmma::accumulator, 16, 16, 16, float> acc[4][4];
    #pragma unroll
    for (int i = 0; i < 4; i++)
        #pragma unroll
        for (int j = 0; j < 4; j++)
            wmma::load_matrix_sync(acc[i][j], &biasTile[wn * 64 + j * 16],
                                   LDBIAS, wmma::mem_row_major);

    const int nk = Kn / BK;
    for (int k0 = 0; k0 < nk; k0++) {
        const int cur = k0 & 1;
        if (k0 + 1 < nk) load_stage(cur ^ 1, (k0 + 1) * BK);
        __pipeline_wait_prior((k0 + 1 < nk) ? 1 : 0);
        __syncthreads();

        #pragma unroll
        for (int kk = 0; kk < BK / 16; kk++) {
            wmma::fragment<wmma::matrix_a, 16, 16, 16, __half, wmma::row_major> af[4];
            wmma::fragment<wmma::matrix_b, 16, 16, 16, __half, wmma::row_major> bf[4];
            #pragma unroll
            for (int i = 0; i < 4; i++)
                wmma::load_matrix_sync(af[i], &As[cur][(wm * 64 + i * 16) * LDA + kk * 16], LDA);
            #pragma unroll
            for (int j = 0; j < 4; j++)
                wmma::load_matrix_sync(bf[j], &Bs[cur][(kk * 16) * LDB + wn * 64 + j * 16], LDB);
            #pragma unroll
            for (int i = 0; i < 4; i++)
                #pragma unroll
                for (int j = 0; j < 4; j++)
                    wmma::mma_sync(acc[i][j], af[i], bf[j], acc[i][j]);
        }
        __syncthreads();
    }

    if constexpr (sizeof(OutT) == 4) {
        // float output (bias already in acc): direct store
        #pragma unroll
        for (int i = 0; i < 4; i++)
            #pragma unroll
            for (int j = 0; j < 4; j++) {
                int row = m0 + wm * 64 + i * 16;
                int col = n0 + wn * 64 + j * 16;
                wmma::store_matrix_sync((float*)&C[(size_t)row * Nn + col],
                                        acc[i][j], Nn, wmma::mem_row_major);
            }
    } else {
        // half output: stage fp32 in double-buffer smem (now dead), convert, write
        float* stage = (float*)smem_raw;     // need 4 * 64*68*4 = 69632 B <= 71680 B
        const int LDS_ = 68;
        float* my = stage + w * (64 * LDS_);
        #pragma unroll
        for (int i = 0; i < 4; i++)
            #pragma unroll
            for (int j = 0; j < 4; j++)
                wmma::store_matrix_sync(&my[(i * 16) * LDS_ + j * 16],
                                        acc[i][j], LDS_, wmma::mem_row_major);
        __syncthreads();
        // 128 rows x 64 half2 columns = 8192 elements, 64 per thread
        #pragma unroll
        for (int it = 0; it < 64; it++) {
            int idx = tid + it * 128;
            int r = idx >> 6, c2 = idx & 63;
            int col = c2 * 2;
            int w2 = (r >> 6) * 2 + (col >> 6);
            const float* src = stage + w2 * (64 * LDS_) + (r & 63) * LDS_ + (col & 63);
            __half2 hv = __floats2half2_rn(src[0], src[1]);
            *(__half2*)&((__half*)C)[(size_t)(m0 + r) * Nn + n0 + col] = hv;
        }
    }
}

__global__ __launch_bounds__(128) void k_gemm_qkv(
    const __half* __restrict__ A,
    const __half* __restrict__ W0, const __half* __restrict__ W1, const __half* __restrict__ W2,
    const float* __restrict__ b0, const float* __restrict__ b1, const float* __restrict__ b2,
    __half* __restrict__ C0, __half* __restrict__ C1, __half* __restrict__ C2)
{
    extern __shared__ char smem_raw[];
    const int z = blockIdx.z;
    const __half* Bw = (z == 0) ? W0 : (z == 1) ? W1 : W2;
    const float* bias = (z == 0) ? b0 : (z == 1) ? b1 : b2;
    __half* C = (z == 0) ? C0 : (z == 1) ? C1 : C2;
    gemm_body<__half>(smem_raw, A, Bw, bias, C);
}

__global__ __launch_bounds__(128) void k_gemm_o(
    const __half* __restrict__ A, const __half* __restrict__ Bw,
    const float* __restrict__ bias, float* __restrict__ C)
{
    extern __shared__ char smem_raw[];
    gemm_body<float>(smem_raw, A, Bw, bias, C);
}

// ---------------- causal flash attention (R2 known-good version, unchanged) ----------------
#define LDT 72

__global__ __launch_bounds__(256) void k_attention(
    const __half* __restrict__ Q, const __half* __restrict__ K,
    const __half* __restrict__ V, __half* __restrict__ Aout)
{
    extern __shared__ char smem_raw[];
    float*  Ss  = (float*)smem_raw;
    float*  PVs = Ss + 64 * LDT;
    __half* Qs  = (__half*)(PVs + 64 * LDT);
    __half* Ks  = Qs + 64 * LDT;
    __half* Vs  = Ks + 64 * LDT;
    __half* Ps  = Vs + 64 * LDT;

    const int qb = blockIdx.x;
    const int h  = blockIdx.y;
    const int b  = blockIdx.z;
    const int tid = threadIdx.x;
    const int w  = tid >> 5;
    const int wm = w >> 1;
    const int wn = w & 1;

    const size_t base = (size_t)b * S_ * D_ + (size_t)h * HD_;

    #pragma unroll
    for (int it = 0; it < 2; it++) {
        int idx = tid + it * 256;
        int r = idx >> 3, c = (idx & 7) * 8;
        *(float4*)&Qs[r * LDT + c] =
            *(const float4*)&Q[base + (size_t)(qb * 64 + r) * D_ + c];
    }

    const int rr = tid >> 2;
    const int c0 = (tid & 3) * 16;
    float m = -INFINITY, l = 0.0f;
    float Ob[16];
    #pragma unroll
    for (int i = 0; i < 16; i++) Ob[i] = 0.0f;

    for (int kb = 0; kb <= qb; kb++) {
        __syncthreads();
        #pragma unroll
        for (int it = 0; it < 2; it++) {
            int idx = tid + it * 256;
            int r = idx >> 3, c = (idx & 7) * 8;
            *(float4*)&Ks[r * LDT + c] =
                *(const float4*)&K[base + (size_t)(kb * 64 + r) * D_ + c];
            *(float4*)&Vs[r * LDT + c] =
                *(const float4*)&V[base + (size_t)(kb * 64 + r) * D_ + c];
        }
        __syncthreads();

        {
            wmma::fragment<wmma::accumulator, 16, 16, 16, float> sc[2];
            wmma::fill_fragment(sc[0], 0.0f);
            wmma::fill_fragment(sc[1], 0.0f);
            #pragma unroll
            for (int kk = 0; kk < 4; kk++) {
                wmma::fragment<wmma::matrix_a, 16, 16, 16, __half, wmma::row_major> aq;
                wmma::load_matrix_sync(aq, &Qs[(wm * 16) * LDT + kk * 16], LDT);
                #pragma unroll
                for (int j = 0; j < 2; j++) {
                    wmma::fragment<wmma::matrix_b, 16, 16, 16, __half, wmma::col_major> bk;
                    wmma::load_matrix_sync(bk, &Ks[(wn * 32 + j * 16) * LDT + kk * 16], LDT);
                    wmma::mma_sync(sc[j], aq, bk, sc[j]);
                }
            }
            #pragma unroll
            for (int j = 0; j < 2; j++)
                wmma::store_matrix_sync(&Ss[(wm * 16) * LDT + wn * 32 + j * 16],
                                        sc[j], LDT, wmma::mem_row_major);
        }
        __syncthreads();

        {
            const int qglob = qb * 64 + rr;
            float sv[16];
            float tmax = -INFINITY;
            #pragma unroll
            for (int i = 0; i < 16; i++) {
                float x = Ss[rr * LDT + c0 + i] * 0.125f;
                int kg = kb * 64 + c0 + i;
                x = (kg <= qglob) ? x : -INFINITY;
                sv[i] = x;
                tmax = fmaxf(tmax, x);
            }
            tmax = fmaxf(tmax, __shfl_xor_sync(0xffffffffu, tmax, 1));
            tmax = fmaxf(tmax, __shfl_xor_sync(0xffffffffu, tmax, 2));
            float mnew  = fmaxf(m, tmax);
            float alpha = (m == -INFINITY) ? 0.0f : __expf(m - mnew);
            float psum = 0.0f;
            #pragma unroll
            for (int i = 0; i < 16; i++) {
                float p = (sv[i] == -INFINITY) ? 0.0f : __expf(sv[i] - mnew);
                psum += p;
                Ps[rr * LDT + c0 + i] = __float2half(p);
            }
            psum += __shfl_xor_sync(0xffffffffu, psum, 1);
            psum += __shfl_xor_sync(0xffffffffu, psum, 2);
            l = l * alpha + psum;
            m = mnew;
            #pragma unroll
            for (int i = 0; i < 16; i++) Ob[i] *= alpha;
        }
        __syncthreads();

        {
            wmma::fragment<wmma::accumulator, 16, 16, 16, float> pv[2];
            wmma::fill_fragment(pv[0], 0.0f);
            wmma::fill_fragment(pv[1], 0.0f);
            #pragma unroll
            for (int kk = 0; kk < 4; kk++) {
                wmma::fragment<wmma::matrix_a, 16, 16, 16, __half, wmma::row_major> ap;
                wmma::load_matrix_sync(ap, &Ps[(wm * 16) * LDT + kk * 16], LDT);
                #pragma unroll
                for (int j = 0; j < 2; j++) {
                    wmma::fragment<wmma::matrix_b, 16, 16, 16, __half, wmma::row_major> bv;
                    wmma::load_matrix_sync(bv, &Vs[(kk * 16) * LDT + wn * 32 + j * 16], LDT);
                    wmma::mma_sync(pv[j], ap, bv, pv[j]);
                }
            }
            #pragma unroll
            for (int j = 0; j < 2; j++)
                wmma::store_matrix_sync(&PVs[(wm * 16) * LDT + wn * 32 + j * 16],
                                        pv[j], LDT, wmma::mem_row_major);
        }
        __syncthreads();
        #pragma unroll
        for (int i = 0; i < 16; i++) Ob[i] += PVs[rr * LDT + c0 + i];
    }

    const float inv_l = 1.0f / l;
    const size_t orow = base + (size_t)(qb * 64 + rr) * D_;
    #pragma unroll
    for (int i = 0; i < 16; i++)
        Aout[orow + c0 + i] = __float2half(Ob[i] * inv_l);
}

// ---------------- launch ----------------
extern "C" void kernel_launch(void* const* d_in, const int* in_sizes, int n_in,
                              void* d_out, int out_size)
{
    const float* hidden = (const float*)d_in[0];
    const float* Wq = (const float*)d_in[1];
    const float* bq = (const float*)d_in[2];
    const float* Wk = (const float*)d_in[3];
    const float* bk = (const float*)d_in[4];
    const float* Wv = (const float*)d_in[5];
    const float* bv = (const float*)d_in[6];
    const float* Wo = (const float*)d_in[7];
    const float* bo = (const float*)d_in[8];
    float* out = (float*)d_out;

    __half *Xh, *Wqh, *Wkh, *Wvh, *Woh, *Qh, *Kh, *Vh, *Ah;
    cudaGetSymbolAddress((void**)&Xh,  g_Xh);
    cudaGetSymbolAddress((void**)&Wqh, g_Wqh);
    cudaGetSymbolAddress((void**)&Wkh, g_Wkh);
    cudaGetSymbolAddress((void**)&Wvh, g_Wvh);
    cudaGetSymbolAddress((void**)&Woh, g_Woh);
    cudaGetSymbolAddress((void**)&Qh,  g_Qh);
    cudaGetSymbolAddress((void**)&Kh,  g_Kh);
    cudaGetSymbolAddress((void**)&Vh,  g_Vh);
    cudaGetSymbolAddress((void**)&Ah,  g_Ah);

    // fp16 conversions
    k_f32_to_f16<<<(M_ * D_ / 4) / 1024, 256>>>(hidden, Xh);
    k_f32_to_f16<<<(D_ * D_ / 4) / 1024, 256>>>(Wq, Wqh);
    k_f32_to_f16<<<(D_ * D_ / 4) / 1024, 256>>>(Wk, Wkh);
    k_f32_to_f16<<<(D_ * D_ / 4) / 1024, 256>>>(Wv, Wvh);
    k_f32_to_f16<<<(D_ * D_ / 4) / 1024, 256>>>(Wo, Woh);

    cudaFuncSetAttribute(k_gemm_qkv, cudaFuncAttributeMaxDynamicSharedMemorySize, GEMM_SMEM);
    cudaFuncSetAttribute(k_gemm_o,   cudaFuncAttributeMaxDynamicSharedMemorySize, GEMM_SMEM);

    // fused QKV projections (one launch, grid.z selects Q/K/V)
    dim3 qkvgrid(D_ / BN, M_ / BM, 3);   // (8, 64, 3)
    k_gemm_qkv<<<qkvgrid, 128, GEMM_SMEM>>>(Xh, Wqh, Wkh, Wvh, bq, bk, bv, Qh, Kh, Vh);

    const int ATT_SMEM = 2 * (64 * LDT * 4) + 4 * (64 * LDT * 2);  // 73728
    cudaFuncSetAttribute(k_attention, cudaFuncAttributeMaxDynamicSharedMemorySize, ATT_SMEM);
    k_attention<<<dim3(S_ / 64, H_, B_), 256, ATT_SMEM>>>(Qh, Kh, Vh, Ah);

    dim3 ogrid(D_ / BN, M_ / BM);   // (8, 64)
    k_gemm_o<<<ogrid, 128, GEMM_SMEM>>>(Ah, Woh, bo, out);
}